// round 13
// baseline (speedup 1.0000x reference)
#include <cuda_runtime.h>

// fired[b,s,r] = x[...,i] * x[...,5+j] * x[...,10+k],  r = i*25 + j*5 + k
// Exact zeros in x act as identity (reference: where(rpu==0,1,rpu)).
//
// R2-R10: ~6.7us kernel plateau across 9 structural variants with nothing
// saturated -> structural floor (launch/ramp T_ovh + single-wave fill/drain
// + short T_CTA critical path). R11 = freeze on R7's best shape (128 thr,
// 16 pos/CTA, thread->rule mapping, immediate-offset LDS, coalesced STG.32)
// with micro-trims: no occupancy clamp (regs free for pipelining), __stcs
// streaming stores (write-once output, evict-first), __ldg staging loads.

static constexpr int F    = 15;           // membership functions per position
static constexpr int R    = 125;          // rules per position
static constexpr int G    = 16;           // positions per CTA
static constexpr int NLD4 = G * F / 4;    // 60 float4 input loads per CTA

__global__ void __launch_bounds__(128)
rules_fire_v11(const float4* __restrict__ x4, float* __restrict__ out)
{
    __shared__ float sx[G * F];           // 240 floats (16 rows x 15)

    const int t   = threadIdx.x;
    const int grp = blockIdx.x;

    // Stage 16x15 inputs (threads 0..59), zero->1 fix at load.
    if (t < NLD4) {
        float4 v = __ldg(&x4[(size_t)grp * NLD4 + t]);
        v.x = (v.x == 0.0f) ? 1.0f : v.x;
        v.y = (v.y == 0.0f) ? 1.0f : v.y;
        v.z = (v.z == 0.0f) ? 1.0f : v.z;
        v.w = (v.w == 0.0f) ? 1.0f : v.w;
        reinterpret_cast<float4*>(sx)[t] = v;
    }
    __syncthreads();

    if (t < R) {
        // One rule decomposition per thread — the only divisions in the kernel.
        const int q = t / 5;
        const int k = t - 5 * q;          // t % 5
        const int i = q / 5;
        const int j = q - 5 * i;          // (t/5) % 5

        const int oa = i;
        const int ob = 5 + j;
        const int oc = 10 + k;

        float* o = out + (size_t)grp * G * R + t;   // + p*R via immediates

        #pragma unroll
        for (int p = 0; p < G; p++) {
            const int rb = p * F;                   // LDS immediate
            const float r = sx[rb + oa] * sx[rb + ob] * sx[rb + oc];
            __stcs(o + p * R, r);                   // streaming (evict-first)
        }
    }
}

// Scalar fallback for positions past the last full group (unused for B=16,S=2048).
__global__ void rules_fire_tail(const float* __restrict__ x, float* __restrict__ out,
                                int pos0, int npos)
{
    const int pos = pos0 + blockIdx.x;
    if (pos >= npos) return;
    __shared__ float sxt[F + 1];
    const int t = threadIdx.x;
    if (t < F) {
        float v = x[(size_t)pos * F + t];
        sxt[t] = (v == 0.0f) ? 1.0f : v;
    }
    __syncthreads();
    if (t < R) {
        const int i = t / 25, j = (t / 5) % 5, k = t % 5;
        out[(size_t)pos * R + t] = sxt[i] * sxt[5 + j] * sxt[10 + k];
    }
}

extern "C" void kernel_launch(void* const* d_in, const int* in_sizes, int n_in,
                              void* d_out, int out_size)
{
    const float* x = (const float*)d_in[0];   // (B, S, 15) float32
    float* out = (float*)d_out;               // (B, S, 125) float32

    const int npos    = in_sizes[0] / F;      // 32768
    const int ngroups = npos / G;             // 2048
    if (ngroups > 0)
        rules_fire_v11<<<ngroups, 128>>>((const float4*)x, out);

    const int tail = npos - ngroups * G;
    if (tail > 0)
        rules_fire_tail<<<tail, 128>>>(x, out, ngroups * G, npos);
}